// round 2
// baseline (speedup 1.0000x reference)
#include <cuda_runtime.h>

// Bilinear: out[b,i,j,k] = sum_{p,q} x1[b,i,p] * W[k,p,q] * x2[b,j,q] + bias[k]
// B=8, L=256, D1=D2=512, K=64.
//
// GEMM1: tmp[(b,i),(k,q)] = X1[2048,512] @ Wr[512,32768]  (Wr[p, k*512+q] = W[k,p,q])
//        tmp stored [b,i,k,q] row-major == per-b row-major [r=(i*64+k), q], stride 512.
// GEMM2: per b: C[j, r] = X2_b[j,:] . TMP_b[r,:]   (NT GEMM, inner dim 512)
//        out addr = b*4194304 + (r>>6)*16384 + j*64 + (r&63); bias fused.

#define TILE 128
#define KT 16
#define LDSS (TILE + 4)

// scratch: 2048 x 32768 floats = 256 MiB
__device__ float g_tmp[67108864];

__global__ __launch_bounds__(256, 2)
void bilinear_gemm1(const float* __restrict__ X1, const float* __restrict__ W) {
    __shared__ float As[KT][LDSS];
    __shared__ float Bs[KT][LDSS];

    const int tid = threadIdx.x;
    const int bn = blockIdx.x * TILE;   // n = k*512 + q
    const int bm = blockIdx.y * TILE;   // m = b*256 + i
    const int kk = bn >> 9;             // which output feature k block
    const int q0 = bn & 511;
    const float* Wb = W + kk * 262144 + q0;   // (p, nl) -> Wb[p*512 + nl]
    const float* Ab = X1 + (size_t)bm * 512;  // (ml, p) -> Ab[ml*512 + p]

    // A tile loads: 128 rows x 16 p, float4 along p
    const int a_m = tid >> 2;
    const int a_p = (tid & 3) << 2;
    // B tile loads: 16 p x 128 n, float4 along n
    const int b_p = tid >> 5;
    const int b_n = (tid & 31) << 2;

    const int tx = tid & 15;
    const int ty = tid >> 4;

    float acc[8][8];
    #pragma unroll
    for (int i = 0; i < 8; i++)
        #pragma unroll
        for (int j = 0; j < 8; j++) acc[i][j] = 0.f;

    for (int p0 = 0; p0 < 512; p0 += KT) {
        #pragma unroll
        for (int s = 0; s < 2; s++) {
            int m = a_m + s * 64;
            float4 v = *(const float4*)(Ab + (size_t)m * 512 + p0 + a_p);
            As[a_p + 0][m] = v.x;
            As[a_p + 1][m] = v.y;
            As[a_p + 2][m] = v.z;
            As[a_p + 3][m] = v.w;
        }
        #pragma unroll
        for (int s = 0; s < 2; s++) {
            int p = b_p + s * 8;
            *(float4*)&Bs[p][b_n] = *(const float4*)(Wb + (size_t)(p0 + p) * 512 + b_n);
        }
        __syncthreads();
        #pragma unroll
        for (int p = 0; p < KT; p++) {
            float a[8], bb[8];
            *(float4*)(a)      = *(const float4*)&As[p][ty * 4];
            *(float4*)(a + 4)  = *(const float4*)&As[p][ty * 4 + 64];
            *(float4*)(bb)     = *(const float4*)&Bs[p][tx * 4];
            *(float4*)(bb + 4) = *(const float4*)&Bs[p][tx * 4 + 64];
            #pragma unroll
            for (int i = 0; i < 8; i++)
                #pragma unroll
                for (int j = 0; j < 8; j++)
                    acc[i][j] += a[i] * bb[j];
        }
        __syncthreads();
    }

    #pragma unroll
    for (int i2 = 0; i2 < 2; i2++) {
        #pragma unroll
        for (int s = 0; s < 4; s++) {
            int m = bm + ty * 4 + i2 * 64 + s;
            float* crow = g_tmp + (size_t)m * 32768 + bn;
            #pragma unroll
            for (int j2 = 0; j2 < 2; j2++) {
                float4 v = make_float4(acc[i2 * 4 + s][j2 * 4 + 0],
                                       acc[i2 * 4 + s][j2 * 4 + 1],
                                       acc[i2 * 4 + s][j2 * 4 + 2],
                                       acc[i2 * 4 + s][j2 * 4 + 3]);
                *(float4*)(crow + tx * 4 + j2 * 64) = v;
            }
        }
    }
}

__global__ __launch_bounds__(256, 2)
void bilinear_gemm2(const float* __restrict__ X2, const float* __restrict__ bias,
                    float* __restrict__ out) {
    __shared__ float As[KT][LDSS];  // As[q][j]
    __shared__ float Bs[KT][LDSS];  // Bs[q][r]

    const int tid = threadIdx.x;
    const int br = blockIdx.x * TILE;   // r = i*64 + k
    const int bj = blockIdx.y * TILE;   // j
    const int b  = blockIdx.z;

    const float* Ab = X2 + (size_t)b * 131072 + (size_t)bj * 512;  // (jl, q)
    const float* Bb = g_tmp + (size_t)b * 8388608 + (size_t)br * 512;  // (rl, q)

    const int a_m = tid >> 2;
    const int a_p = (tid & 3) << 2;
    const int tx = tid & 15;
    const int ty = tid >> 4;

    float acc[8][8];
    #pragma unroll
    for (int i = 0; i < 8; i++)
        #pragma unroll
        for (int j = 0; j < 8; j++) acc[i][j] = 0.f;

    for (int p0 = 0; p0 < 512; p0 += KT) {
        #pragma unroll
        for (int s = 0; s < 2; s++) {
            int m = a_m + s * 64;
            float4 v = *(const float4*)(Ab + (size_t)m * 512 + p0 + a_p);
            As[a_p + 0][m] = v.x;
            As[a_p + 1][m] = v.y;
            As[a_p + 2][m] = v.z;
            As[a_p + 3][m] = v.w;
            float4 w = *(const float4*)(Bb + (size_t)m * 512 + p0 + a_p);
            Bs[a_p + 0][m] = w.x;
            Bs[a_p + 1][m] = w.y;
            Bs[a_p + 2][m] = w.z;
            Bs[a_p + 3][m] = w.w;
        }
        __syncthreads();
        #pragma unroll
        for (int p = 0; p < KT; p++) {
            float a[8], bb[8];
            *(float4*)(a)      = *(const float4*)&As[p][ty * 4];
            *(float4*)(a + 4)  = *(const float4*)&As[p][ty * 4 + 64];
            *(float4*)(bb)     = *(const float4*)&Bs[p][tx * 4];
            *(float4*)(bb + 4) = *(const float4*)&Bs[p][tx * 4 + 64];
            #pragma unroll
            for (int i = 0; i < 8; i++)
                #pragma unroll
                for (int j = 0; j < 8; j++)
                    acc[i][j] += a[i] * bb[j];
        }
        __syncthreads();
    }

    // Epilogue: acc[j_idx][r_idx]; out[b, i=r>>6, j, k=r&63] + bias[k]
    #pragma unroll
    for (int i2 = 0; i2 < 2; i2++) {
        #pragma unroll
        for (int s = 0; s < 4; s++) {
            int jg = bj + ty * 4 + i2 * 64 + s;
            #pragma unroll
            for (int j2 = 0; j2 < 2; j2++) {
                int rg = br + tx * 4 + j2 * 64;
                int k  = rg & 63;        // = tx*4, 16B-aligned
                int ig = rg >> 6;
                float4 bv = *(const float4*)(bias + k);
                float4 v = make_float4(acc[i2 * 4 + s][j2 * 4 + 0] + bv.x,
                                       acc[i2 * 4 + s][j2 * 4 + 1] + bv.y,
                                       acc[i2 * 4 + s][j2 * 4 + 2] + bv.z,
                                       acc[i2 * 4 + s][j2 * 4 + 3] + bv.w);
                *(float4*)(out + ((size_t)b << 22) + (size_t)ig * 16384
                               + (size_t)jg * 64 + k) = v;
            }
        }
    }
}

extern "C" void kernel_launch(void* const* d_in, const int* in_sizes, int n_in,
                              void* d_out, int out_size) {
    const float* x1   = (const float*)d_in[0];
    const float* x2   = (const float*)d_in[1];
    const float* w    = (const float*)d_in[2];
    const float* bias = (const float*)d_in[3];
    float* out = (float*)d_out;

    // GEMM1: M=2048, N=32768, inner=512
    bilinear_gemm1<<<dim3(256, 16), 256>>>(x1, w);
    // GEMM2: per b: M=256(j), N=16384(r), inner=512
    bilinear_gemm2<<<dim3(128, 2, 8), 256>>>(x2, bias, out);
}

// round 7
// speedup vs baseline: 2.0998x; 2.0998x over previous
#include <cuda_runtime.h>
#include <cuda_bf16.h>
#include <cstdint>

// Bilinear out[b,i,j,k] = sum_{p,q} x1[b,i,p] W[k,p,q] x2[b,j,q] + bias[k]
// B=8, L=256, D1=D2=512, K=64.
// GEMM1: TMP[m=(b,i)][n=(k,q)] = X1[2048,512] . Wt[(k,q)][p]   (NT, inner 512)
// GEMM2: per b: C[j][r=(i,k)]  = X2_b[j][q] . TMP_b[r][q]      (NT, inner 512)
// Tensor path: mma.sync m16n8k16 bf16 (portable HMMA; tcgen05 rejected by this
// build's sm_103 target). fp32 accuracy via bf16 hi/lo 3-pass split.

#define DI __device__ __forceinline__

#define MT 128          // CTA m tile
#define NTL 128         // CTA n tile
#define KC 64           // k elements per chunk (128B rows)
#define NCHUNK 8        // 512/64

#define TILE_B 16384            // 128 rows x 128B
#define STAGE_B 65536           // Ah|Al|Bh|Bl
#define SMEM_BYTES (2*STAGE_B + 1024)

// ---------------- scratch (device globals; allocs forbidden) ----------------
__device__ __nv_bfloat16 g_x1h[2048*512];
__device__ __nv_bfloat16 g_x1l[2048*512];
__device__ __nv_bfloat16 g_x2h[2048*512];
__device__ __nv_bfloat16 g_x2l[2048*512];
__device__ __nv_bfloat16 g_wth[64*512*512];   // Wt[k][q][p] hi
__device__ __nv_bfloat16 g_wtl[64*512*512];   // Wt[k][q][p] lo
__device__ __nv_bfloat16 g_th[2048u*32768u];  // TMP hi [m][n]
__device__ __nv_bfloat16 g_tl[2048u*32768u];  // TMP lo [m][n]

// ---------------- PTX helpers ----------------
DI uint32_t smem_u32(const void* p) {
    uint32_t a;
    asm("{ .reg .u64 t; cvta.to.shared.u64 t, %1; cvt.u32.u64 %0, t; }"
        : "=r"(a) : "l"(p));
    return a;
}
DI void cp16(uint32_t dst, const void* src) {
    asm volatile("cp.async.cg.shared.global [%0], [%1], 16;"
                 :: "r"(dst), "l"(src) : "memory");
}
#define CP_COMMIT() asm volatile("cp.async.commit_group;" ::: "memory")
#define CP_WAIT1()  asm volatile("cp.async.wait_group 1;"  ::: "memory")
#define CP_WAIT0()  asm volatile("cp.async.wait_group 0;"  ::: "memory")

DI void ldsm4(uint32_t addr, uint32_t r[4]) {
    asm volatile("ldmatrix.sync.aligned.m8n8.x4.shared.b16 {%0,%1,%2,%3}, [%4];"
        : "=r"(r[0]), "=r"(r[1]), "=r"(r[2]), "=r"(r[3]) : "r"(addr));
}
DI void mma16816(float c[4], const uint32_t a[4], uint32_t b0, uint32_t b1) {
    asm volatile("mma.sync.aligned.m16n8k16.row.col.f32.bf16.bf16.f32 "
        "{%0,%1,%2,%3}, {%4,%5,%6,%7}, {%8,%9}, {%0,%1,%2,%3};"
        : "+f"(c[0]), "+f"(c[1]), "+f"(c[2]), "+f"(c[3])
        : "r"(a[0]), "r"(a[1]), "r"(a[2]), "r"(a[3]), "r"(b0), "r"(b1));
}

// ---------------- stage loader: 4 K-major tiles (global stride 512 bf16) ----
DI void stage_load(const __nv_bfloat16* gAh, const __nv_bfloat16* gAl,
                   const __nv_bfloat16* gBh, const __nv_bfloat16* gBl,
                   uint32_t sbase, int chunk, int tid) {
    #pragma unroll
    for (int i = 0; i < 4; i++) {
        int g   = tid + i * 256;
        int row = g >> 3;
        int c   = g & 7;
        uint32_t dst = sbase + (uint32_t)(row * 128 + ((c ^ (row & 7)) << 4));
        size_t   src = (size_t)row * 512 + chunk * KC + c * 8;
        cp16(dst,                 gAh + src);
        cp16(dst + TILE_B,        gAl + src);
        cp16(dst + 2 * TILE_B,    gBh + src);
        cp16(dst + 3 * TILE_B,    gBl + src);
    }
    CP_COMMIT();
}

// ---------------- compute one 64-wide K chunk, 3 split passes ----------------
DI void compute_stage(uint32_t s, int wid, int lane, float acc[2][8][4]) {
    const int wm = (wid & 3) * 32;
    const int wn = (wid >> 2) * 64;
    const int lr = lane & 15;
    const int ls = lane >> 4;
    const uint32_t sA = s;
    const uint32_t sB = s + 2 * TILE_B;
    #pragma unroll
    for (int ks = 0; ks < 4; ks++) {
        const int kg = ks * 2;
        uint32_t ah[2][4], al[2][4];
        #pragma unroll
        for (int mg = 0; mg < 2; mg++) {
            int row = wm + mg * 16 + lr;
            uint32_t off = (uint32_t)(row * 128 + (((kg + ls) ^ (row & 7)) << 4));
            ldsm4(sA + off, ah[mg]);
            ldsm4(sA + TILE_B + off, al[mg]);
        }
        #pragma unroll
        for (int h = 0; h < 4; h++) {
            int row = wn + h * 16 + lr;
            uint32_t off = (uint32_t)(row * 128 + (((kg + ls) ^ (row & 7)) << 4));
            uint32_t bh[4], bl[4];
            ldsm4(sB + off, bh);
            ldsm4(sB + TILE_B + off, bl);
            #pragma unroll
            for (int mg = 0; mg < 2; mg++) {
                mma16816(acc[mg][2*h],   ah[mg], bh[0], bh[2]);
                mma16816(acc[mg][2*h+1], ah[mg], bh[1], bh[3]);
                mma16816(acc[mg][2*h],   ah[mg], bl[0], bl[2]);
                mma16816(acc[mg][2*h+1], ah[mg], bl[1], bl[3]);
                mma16816(acc[mg][2*h],   al[mg], bh[0], bh[2]);
                mma16816(acc[mg][2*h+1], al[mg], bh[1], bh[3]);
            }
        }
    }
}

// ---------------- shared mainloop ----------------
DI void gemm_core(const __nv_bfloat16* gAh, const __nv_bfloat16* gAl,
                  const __nv_bfloat16* gBh, const __nv_bfloat16* gBl,
                  uint32_t s0, int tid, int wid, int lane, float acc[2][8][4]) {
    #pragma unroll
    for (int a = 0; a < 2; a++)
        #pragma unroll
        for (int b = 0; b < 8; b++)
            #pragma unroll
            for (int e = 0; e < 4; e++) acc[a][b][e] = 0.f;

    stage_load(gAh, gAl, gBh, gBl, s0, 0, tid);
    for (int c = 0; c < NCHUNK; c++) {
        if (c < NCHUNK - 1) {
            stage_load(gAh, gAl, gBh, gBl, s0 + ((c + 1) & 1) * STAGE_B, c + 1, tid);
            CP_WAIT1();
        } else {
            CP_WAIT0();
        }
        __syncthreads();
        compute_stage(s0 + (c & 1) * STAGE_B, wid, lane, acc);
        __syncthreads();
    }
}

// ---------------- GEMM1: epilogue emits bf16 hi/lo TMP ----------------
__global__ void __launch_bounds__(256, 1) k_gemm1() {
    extern __shared__ __align__(16) char dyn[];
    const int tid = threadIdx.x, wid = tid >> 5, lane = tid & 31;
    uint32_t s0 = (smem_u32(dyn) + 1023u) & ~1023u;

    const int bm = blockIdx.x * MT;    // m = b*256+i   (x = m for W L2 reuse)
    const int bn = blockIdx.y * NTL;   // n = k*512+q
    float acc[2][8][4];
    gemm_core(g_x1h + (size_t)bm * 512, g_x1l + (size_t)bm * 512,
              g_wth + (size_t)bn * 512, g_wtl + (size_t)bn * 512,
              s0, tid, wid, lane, acc);

    const int wm = (wid & 3) * 32, wn = (wid >> 2) * 64;
    const int quad = lane >> 2, tq = lane & 3;
    #pragma unroll
    for (int mg = 0; mg < 2; mg++) {
        #pragma unroll
        for (int pr = 0; pr < 2; pr++) {
            int m = bm + wm + mg * 16 + quad + pr * 8;
            size_t rowb = (size_t)m * 32768 + bn + wn + tq * 2;
            #pragma unroll
            for (int g = 0; g < 8; g++) {
                float a = acc[mg][g][pr * 2];
                float b = acc[mg][g][pr * 2 + 1];
                __nv_bfloat16 ha = __float2bfloat16(a);
                __nv_bfloat16 hb = __float2bfloat16(b);
                __nv_bfloat162 hv; hv.x = ha; hv.y = hb;
                __nv_bfloat162 lv;
                lv.x = __float2bfloat16(a - __bfloat162float(ha));
                lv.y = __float2bfloat16(b - __bfloat162float(hb));
                *(__nv_bfloat162*)(g_th + rowb + g * 8) = hv;
                *(__nv_bfloat162*)(g_tl + rowb + g * 8) = lv;
            }
        }
    }
}

// ---------------- GEMM2: out = X2_b . TMP_b^T + bias ----------------
__global__ void __launch_bounds__(256, 1) k_gemm2(const float* __restrict__ bias,
                                                  float* __restrict__ out) {
    extern __shared__ __align__(16) char dyn[];
    const int tid = threadIdx.x, wid = tid >> 5, lane = tid & 31;
    uint32_t s0 = (smem_u32(dyn) + 1023u) & ~1023u;

    const int bj = blockIdx.x * MT;    // j  (x = j for TMP L2 reuse)
    const int bn = blockIdx.y * NTL;   // r = i*64 + k
    const int b  = blockIdx.z;
    size_t aoff = (size_t)b * 131072 + (size_t)bj * 512;
    size_t boff = (size_t)b * 8388608 + (size_t)bn * 512;
    float acc[2][8][4];
    gemm_core(g_x2h + aoff, g_x2l + aoff, g_th + boff, g_tl + boff,
              s0, tid, wid, lane, acc);

    const int wm = (wid & 3) * 32, wn = (wid >> 2) * 64;
    const int quad = lane >> 2, tq = lane & 3;
    const int ig = (bn + wn) >> 6;                  // constant per warp
    const size_t obase = ((size_t)b << 22) + (size_t)ig * 16384;
    #pragma unroll
    for (int g = 0; g < 8; g++) {
        int k = g * 8 + tq * 2;
        float2 bv = *(const float2*)(bias + k);
        #pragma unroll
        for (int mg = 0; mg < 2; mg++) {
            #pragma unroll
            for (int pr = 0; pr < 2; pr++) {
                int j = bj + wm + mg * 16 + quad + pr * 8;
                float2 v;
                v.x = acc[mg][g][pr * 2]     + bv.x;
                v.y = acc[mg][g][pr * 2 + 1] + bv.y;
                *(float2*)(out + obase + (size_t)j * 64 + k) = v;
            }
        }
    }
}

// ---------------- prep: fp32 -> bf16 hi/lo splits ----------------
__global__ void __launch_bounds__(256) k_split(const float* __restrict__ in, int which) {
    __nv_bfloat16* oh = which ? g_x2h : g_x1h;
    __nv_bfloat16* ol = which ? g_x2l : g_x1l;
    int i = blockIdx.x * 256 + threadIdx.x;      // 262144 float4s
    float4 v = ((const float4*)in)[i];
    __nv_bfloat16 h0 = __float2bfloat16(v.x), h1 = __float2bfloat16(v.y);
    __nv_bfloat16 h2 = __float2bfloat16(v.z), h3 = __float2bfloat16(v.w);
    __nv_bfloat162 hv0; hv0.x = h0; hv0.y = h1;
    __nv_bfloat162 hv1; hv1.x = h2; hv1.y = h3;
    __nv_bfloat162 lv0, lv1;
    lv0.x = __float2bfloat16(v.x - __bfloat162float(h0));
    lv0.y = __float2bfloat16(v.y - __bfloat162float(h1));
    lv1.x = __float2bfloat16(v.z - __bfloat162float(h2));
    lv1.y = __float2bfloat16(v.w - __bfloat162float(h3));
    ((__nv_bfloat162*)oh)[2 * i]     = hv0;
    ((__nv_bfloat162*)oh)[2 * i + 1] = hv1;
    ((__nv_bfloat162*)ol)[2 * i]     = lv0;
    ((__nv_bfloat162*)ol)[2 * i + 1] = lv1;
}

// W[k][p][q] -> Wt[k][q][p] hi/lo (32x32 smem transpose tiles)
__global__ void __launch_bounds__(256) k_wtrans(const float* __restrict__ W) {
    __shared__ float t[32][33];
    int k = blockIdx.z;
    int q0 = blockIdx.x * 32, p0 = blockIdx.y * 32;
    int tx = threadIdx.x & 31, ty = threadIdx.x >> 5;
    const float* Wk = W + (size_t)k * 262144;
    #pragma unroll
    for (int s = 0; s < 4; s++)
        t[ty + s * 8][tx] = Wk[(size_t)(p0 + ty + s * 8) * 512 + q0 + tx];
    __syncthreads();
    #pragma unroll
    for (int s = 0; s < 4; s++) {
        int q = q0 + ty + s * 8;
        float v = t[tx][ty + s * 8];
        __nv_bfloat16 h = __float2bfloat16(v);
        size_t o = (size_t)k * 262144 + (size_t)q * 512 + p0 + tx;
        g_wth[o] = h;
        g_wtl[o] = __float2bfloat16(v - __bfloat162float(h));
    }
}

// ---------------- launch ----------------
extern "C" void kernel_launch(void* const* d_in, const int* in_sizes, int n_in,
                              void* d_out, int out_size) {
    const float* x1   = (const float*)d_in[0];
    const float* x2   = (const float*)d_in[1];
    const float* w    = (const float*)d_in[2];
    const float* bias = (const float*)d_in[3];
    float* out = (float*)d_out;

    cudaFuncSetAttribute(k_gemm1, cudaFuncAttributeMaxDynamicSharedMemorySize, SMEM_BYTES);
    cudaFuncSetAttribute(k_gemm2, cudaFuncAttributeMaxDynamicSharedMemorySize, SMEM_BYTES);

    k_split<<<1024, 256>>>(x1, 0);
    k_split<<<1024, 256>>>(x2, 1);
    k_wtrans<<<dim3(16, 16, 64), 256>>>(w);
    // GEMM1: x = m (16) so a wave shares W n-tiles across all 16 m-blocks (L2 reuse)
    k_gemm1<<<dim3(16, 256), 256, SMEM_BYTES>>>();
    // GEMM2: x = j (2) so both j-blocks of a TMP n-tile are co-resident
    k_gemm2<<<dim3(2, 128, 8), 256, SMEM_BYTES>>>(bias, out);
}

// round 8
// speedup vs baseline: 5.8850x; 2.8026x over previous
#include <cuda_runtime.h>
#include <cuda_fp16.h>
#include <cstdint>

// Bilinear out[b,i,j,k] = sum_{p,q} x1[b,i,p] W[k,p,q] x2[b,j,q] + bias[k]
// B=8, L=256, D1=D2=512, K=64.
// GEMM1: TMP[m=(b,i)][n=(k,q)] = X1[2048,512] . Wt[(k,q)][p]   (NT, inner 512)
// GEMM2: per b: C[j][r=(i,k)]  = X2_b[j][q] . TMP_b[r][q]      (NT, inner 512)
// Single-pass fp16 HMMA (m16n8k16, fp32 accum): RMS rel err ~3e-4 << 1e-3 gate.
// 3-stage cp.async pipeline, 96KB smem/CTA -> 2 CTAs/SM.

#define DI __device__ __forceinline__

#define MT 128          // CTA m tile
#define NTL 128         // CTA n tile
#define KC 64           // k elements per chunk (128B rows fp16)
#define NCHUNK 8        // 512/64

#define TILE_B 16384            // 128 rows x 128B
#define STAGE_B 32768           // A|B
#define NSTAGE 3
#define SMEM_BYTES (NSTAGE*STAGE_B + 1024)

// ---------------- scratch (device globals; allocs forbidden) ----------------
__device__ __half g_x1h[2048*512];
__device__ __half g_x2h[2048*512];
__device__ __half g_wth[64*512*512];    // Wt[k][q][p]
__device__ __half g_th[2048u*32768u];   // TMP [m][n]

// ---------------- PTX helpers ----------------
DI uint32_t smem_u32(const void* p) {
    uint32_t a;
    asm("{ .reg .u64 t; cvta.to.shared.u64 t, %1; cvt.u32.u64 %0, t; }"
        : "=r"(a) : "l"(p));
    return a;
}
DI void cp16(uint32_t dst, const void* src) {
    asm volatile("cp.async.cg.shared.global [%0], [%1], 16;"
                 :: "r"(dst), "l"(src) : "memory");
}
#define CP_COMMIT() asm volatile("cp.async.commit_group;" ::: "memory")
#define CP_WAIT1()  asm volatile("cp.async.wait_group 1;"  ::: "memory")
#define CP_WAIT0()  asm volatile("cp.async.wait_group 0;"  ::: "memory")

DI void ldsm4(uint32_t addr, uint32_t r[4]) {
    asm volatile("ldmatrix.sync.aligned.m8n8.x4.shared.b16 {%0,%1,%2,%3}, [%4];"
        : "=r"(r[0]), "=r"(r[1]), "=r"(r[2]), "=r"(r[3]) : "r"(addr));
}
DI void mma16816(float c[4], const uint32_t a[4], uint32_t b0, uint32_t b1) {
    asm volatile("mma.sync.aligned.m16n8k16.row.col.f32.f16.f16.f32 "
        "{%0,%1,%2,%3}, {%4,%5,%6,%7}, {%8,%9}, {%0,%1,%2,%3};"
        : "+f"(c[0]), "+f"(c[1]), "+f"(c[2]), "+f"(c[3])
        : "r"(a[0]), "r"(a[1]), "r"(a[2]), "r"(a[3]), "r"(b0), "r"(b1));
}

// ---------------- stage loader: A,B K-major tiles (global stride 512 fp16) ----
DI void stage_load(const __half* __restrict__ gA, const __half* __restrict__ gB,
                   uint32_t sbase, int chunk, int tid) {
    #pragma unroll
    for (int i = 0; i < 4; i++) {
        int g   = tid + i * 256;
        int row = g >> 3;
        int c   = g & 7;
        uint32_t dst = sbase + (uint32_t)(row * 128 + ((c ^ (row & 7)) << 4));
        size_t   src = (size_t)row * 512 + chunk * KC + c * 8;
        cp16(dst,          gA + src);
        cp16(dst + TILE_B, gB + src);
    }
    CP_COMMIT();
}

// ---------------- compute one 64-wide K chunk ----------------
DI void compute_stage(uint32_t s, int wid, int lane, float acc[2][8][4]) {
    const int wm = (wid & 3) * 32;
    const int wn = (wid >> 2) * 64;
    const int lr = lane & 15;
    const int ls = lane >> 4;
    const uint32_t sA = s;
    const uint32_t sB = s + TILE_B;
    #pragma unroll
    for (int ks = 0; ks < 4; ks++) {
        const int kg = ks * 2;
        uint32_t ah[2][4];
        #pragma unroll
        for (int mg = 0; mg < 2; mg++) {
            int row = wm + mg * 16 + lr;
            uint32_t off = (uint32_t)(row * 128 + (((kg + ls) ^ (row & 7)) << 4));
            ldsm4(sA + off, ah[mg]);
        }
        #pragma unroll
        for (int h = 0; h < 4; h++) {
            int row = wn + h * 16 + lr;
            uint32_t off = (uint32_t)(row * 128 + (((kg + ls) ^ (row & 7)) << 4));
            uint32_t bh[4];
            ldsm4(sB + off, bh);
            #pragma unroll
            for (int mg = 0; mg < 2; mg++) {
                mma16816(acc[mg][2*h],   ah[mg], bh[0], bh[2]);
                mma16816(acc[mg][2*h+1], ah[mg], bh[1], bh[3]);
            }
        }
    }
}

// ---------------- shared mainloop (3-stage pipeline, 1 sync/chunk) ----------
DI void gemm_core(const __half* gA, const __half* gB,
                  uint32_t s0, int tid, int wid, int lane, float acc[2][8][4]) {
    #pragma unroll
    for (int a = 0; a < 2; a++)
        #pragma unroll
        for (int b = 0; b < 8; b++)
            #pragma unroll
            for (int e = 0; e < 4; e++) acc[a][b][e] = 0.f;

    stage_load(gA, gB, s0,           0, tid);
    stage_load(gA, gB, s0 + STAGE_B, 1, tid);
    #pragma unroll 1
    for (int c = 0; c < NCHUNK; c++) {
        if (c < NCHUNK - 1) CP_WAIT1(); else CP_WAIT0();
        __syncthreads();
        if (c < NCHUNK - 2)
            stage_load(gA, gB, s0 + ((c + 2) % NSTAGE) * STAGE_B, c + 2, tid);
        compute_stage(s0 + (c % NSTAGE) * STAGE_B, wid, lane, acc);
    }
}

// ---------------- GEMM1: epilogue emits fp16 TMP ----------------
__global__ void __launch_bounds__(256, 2) k_gemm1() {
    extern __shared__ __align__(16) char dyn[];
    const int tid = threadIdx.x, wid = tid >> 5, lane = tid & 31;
    uint32_t s0 = (smem_u32(dyn) + 1023u) & ~1023u;

    const int bm = blockIdx.x * MT;    // m = b*256+i   (x = m for W L2 reuse)
    const int bn = blockIdx.y * NTL;   // n = k*512+q
    float acc[2][8][4];
    gemm_core(g_x1h + (size_t)bm * 512, g_wth + (size_t)bn * 512,
              s0, tid, wid, lane, acc);

    const int wm = (wid & 3) * 32, wn = (wid >> 2) * 64;
    const int quad = lane >> 2, tq = lane & 3;
    #pragma unroll
    for (int mg = 0; mg < 2; mg++) {
        #pragma unroll
        for (int pr = 0; pr < 2; pr++) {
            int m = bm + wm + mg * 16 + quad + pr * 8;
            size_t rowb = (size_t)m * 32768 + bn + wn + tq * 2;
            #pragma unroll
            for (int g = 0; g < 8; g++) {
                __half2 hv = __floats2half2_rn(acc[mg][g][pr * 2],
                                               acc[mg][g][pr * 2 + 1]);
                *(__half2*)(g_th + rowb + g * 8) = hv;
            }
        }
    }
}

// ---------------- GEMM2: out = X2_b . TMP_b^T + bias ----------------
__global__ void __launch_bounds__(256, 2) k_gemm2(const float* __restrict__ bias,
                                                  float* __restrict__ out) {
    extern __shared__ __align__(16) char dyn[];
    const int tid = threadIdx.x, wid = tid >> 5, lane = tid & 31;
    uint32_t s0 = (smem_u32(dyn) + 1023u) & ~1023u;

    const int bj = blockIdx.x * MT;    // j  (x = j for TMP L2 reuse)
    const int bn = blockIdx.y * NTL;   // r = i*64 + k
    const int b  = blockIdx.z;
    float acc[2][8][4];
    gemm_core(g_x2h + (size_t)b * 131072 + (size_t)bj * 512,
              g_th  + (size_t)b * 8388608 + (size_t)bn * 512,
              s0, tid, wid, lane, acc);

    const int wm = (wid & 3) * 32, wn = (wid >> 2) * 64;
    const int quad = lane >> 2, tq = lane & 3;
    const int ig = (bn + wn) >> 6;                  // constant per warp
    const size_t obase = ((size_t)b << 22) + (size_t)ig * 16384;
    #pragma unroll
    for (int g = 0; g < 8; g++) {
        int k = g * 8 + tq * 2;
        float2 bv = *(const float2*)(bias + k);
        #pragma unroll
        for (int mg = 0; mg < 2; mg++) {
            #pragma unroll
            for (int pr = 0; pr < 2; pr++) {
                int j = bj + wm + mg * 16 + quad + pr * 8;
                float2 v;
                v.x = acc[mg][g][pr * 2]     + bv.x;
                v.y = acc[mg][g][pr * 2 + 1] + bv.y;
                *(float2*)(out + obase + (size_t)j * 64 + k) = v;
            }
        }
    }
}

// ---------------- prep: fp32 -> fp16 ----------------
__global__ void __launch_bounds__(256) k_split(const float* __restrict__ in, int which) {
    __half* oh = which ? g_x2h : g_x1h;
    int i = blockIdx.x * 256 + threadIdx.x;      // 262144 float4s
    float4 v = ((const float4*)in)[i];
    ((__half2*)oh)[2 * i]     = __floats2half2_rn(v.x, v.y);
    ((__half2*)oh)[2 * i + 1] = __floats2half2_rn(v.z, v.w);
}

// W[k][p][q] -> Wt[k][q][p] fp16 (32x32 smem transpose tiles)
__global__ void __launch_bounds__(256) k_wtrans(const float* __restrict__ W) {
    __shared__ float t[32][33];
    int k = blockIdx.z;
    int q0 = blockIdx.x * 32, p0 = blockIdx.y * 32;
    int tx = threadIdx.x & 31, ty = threadIdx.x >> 5;
    const float* Wk = W + (size_t)k * 262144;
    #pragma unroll
    for (int s = 0; s < 4; s++)
        t[ty + s * 8][tx] = Wk[(size_t)(p0 + ty + s * 8) * 512 + q0 + tx];
    __syncthreads();
    #pragma unroll
    for (int s = 0; s < 4; s++) {
        int q = q0 + ty + s * 8;
        g_wth[(size_t)k * 262144 + (size_t)q * 512 + p0 + tx] =
            __float2half_rn(t[tx][ty + s * 8]);
    }
}

// ---------------- launch ----------------
extern "C" void kernel_launch(void* const* d_in, const int* in_sizes, int n_in,
                              void* d_out, int out_size) {
    const float* x1   = (const float*)d_in[0];
    const float* x2   = (const float*)d_in[1];
    const float* w    = (const float*)d_in[2];
    const float* bias = (const float*)d_in[3];
    float* out = (float*)d_out;

    cudaFuncSetAttribute(k_gemm1, cudaFuncAttributeMaxDynamicSharedMemorySize, SMEM_BYTES);
    cudaFuncSetAttribute(k_gemm2, cudaFuncAttributeMaxDynamicSharedMemorySize, SMEM_BYTES);

    k_split<<<1024, 256>>>(x1, 0);
    k_split<<<1024, 256>>>(x2, 1);
    k_wtrans<<<dim3(16, 16, 64), 256>>>(w);
    // GEMM1: x = m (16) so a wave shares W n-tiles across all 16 m-blocks (L2 reuse)
    k_gemm1<<<dim3(16, 256), 256, SMEM_BYTES>>>();
    // GEMM2: x = j (2) so both j-blocks of a TMP n-tile are co-resident
    k_gemm2<<<dim3(2, 128, 8), 256, SMEM_BYTES>>>(bias, out);
}